// round 15
// baseline (speedup 1.0000x reference)
#include <cuda_runtime.h>
#include <math.h>

// GPT-2 small forward: B=2, T=1024, D=768, H=12, HD=64, L=12, V=50257
#define B_   2
#define T_   1024
#define D_   768
#define H_   12
#define HD_  64
#define L_   12
#define V_   50257
#define FF_  3072
#define BT_  (B_*T_)
#define EPS_ 1e-5f

typedef unsigned long long ull;

// ---------------- packed f32x2 helpers ----------------
__device__ __forceinline__ ull pack2(float x, float y) {
    ull r;
    asm("mov.b64 %0, {%1, %2};" : "=l"(r)
        : "r"(__float_as_uint(x)), "r"(__float_as_uint(y)));
    return r;
}
__device__ __forceinline__ ull splat2(float x) {
    ull r;
    asm("mov.b64 %0, {%1, %1};" : "=l"(r) : "r"(__float_as_uint(x)));
    return r;
}
__device__ __forceinline__ void fma2(ull& d, ull a, ull b) {
    asm("fma.rn.f32x2 %0, %1, %2, %0;" : "+l"(d) : "l"(a), "l"(b));
}
__device__ __forceinline__ void mul2(ull& d, ull a) {
    asm("mul.rn.f32x2 %0, %0, %1;" : "+l"(d) : "l"(a));
}
__device__ __forceinline__ void unpack2(ull v, float& lo, float& hi) {
    unsigned a, b;
    asm("mov.b64 {%0, %1}, %2;" : "=r"(a), "=r"(b) : "l"(v));
    lo = __uint_as_float(a); hi = __uint_as_float(b);
}

// ---------------- scratch (no cudaMalloc allowed) ----------------
__device__ float g_x  [BT_*D_];
__device__ float g_h  [BT_*D_];
__device__ float g_qkv[BT_*3*D_];
__device__ float g_y  [BT_*D_];
__device__ float g_ff [BT_*FF_];

// ---------------- tf32 helpers ----------------
__device__ __forceinline__ unsigned f2tf32(float f) {
    unsigned u;
    asm("cvt.rna.tf32.f32 %0, %1;" : "=r"(u) : "f"(f));
    return u;
}
__device__ __forceinline__ void mma_tf32(float* c, const unsigned* a, const unsigned* b) {
    asm volatile(
        "mma.sync.aligned.m16n8k8.row.col.f32.tf32.tf32.f32 "
        "{%0,%1,%2,%3}, {%4,%5,%6,%7}, {%8,%9}, {%0,%1,%2,%3};"
        : "+f"(c[0]), "+f"(c[1]), "+f"(c[2]), "+f"(c[3])
        : "r"(a[0]), "r"(a[1]), "r"(a[2]), "r"(a[3]), "r"(b[0]), "r"(b[1]));
}

// ---------------- embedding ----------------
__global__ void embed_kernel(const int* __restrict__ idx,
                             const float* __restrict__ tok,
                             const float* __restrict__ pos,
                             float* __restrict__ x) {
    int i = blockIdx.x * blockDim.x + threadIdx.x;
    if (i >= BT_*D_) return;
    int bt = i / D_, d = i - bt * D_;
    int t = bt % T_;
    x[i] = tok[(size_t)idx[bt]*D_ + d] + pos[(size_t)t*D_ + d];
}

// ---------------- layernorm ----------------
__global__ void ln_kernel(const float* __restrict__ x,
                          const float* __restrict__ g,
                          const float* __restrict__ b,
                          float* __restrict__ out) {
    __shared__ float red[256];
    int row = blockIdx.x;
    int tid = threadIdx.x;
    const float* xr = x + (size_t)row * D_;
    float v0 = xr[tid], v1 = xr[tid+256], v2 = xr[tid+512];
    red[tid] = v0 + v1 + v2;
    __syncthreads();
    #pragma unroll
    for (int s = 128; s > 0; s >>= 1) {
        if (tid < s) red[tid] += red[tid+s];
        __syncthreads();
    }
    float mean = red[0] * (1.0f / D_);
    __syncthreads();
    float d0 = v0-mean, d1 = v1-mean, d2 = v2-mean;
    red[tid] = d0*d0 + d1*d1 + d2*d2;
    __syncthreads();
    #pragma unroll
    for (int s = 128; s > 0; s >>= 1) {
        if (tid < s) red[tid] += red[tid+s];
        __syncthreads();
    }
    float rstd = rsqrtf(red[0] * (1.0f / D_) + EPS_);
    float* orow = out + (size_t)row * D_;
    orow[tid    ] = d0 * rstd * g[tid    ] + b[tid    ];
    orow[tid+256] = d1 * rstd * g[tid+256] + b[tid+256];
    orow[tid+512] = d2 * rstd * g[tid+512] + b[tid+512];
}

// ---------------- tf32 tensor-core GEMM (fragment-shuffled SMEM) ----------------
// C[M, ·] = A[M,K] @ Wsel[K,Nw] (+bias)(+gelu)(+residual), output stride ldc.
// Wsel per column-block: sel = (blockIdx.y*BN)/Nw -> w0/w1/w2 (QKV fusion).
// SMEM holds tiles pre-permuted into m16n8k8 fragment order:
//   A slice (kk, mtile): 128 words laid out [lane][word] -> fragment = 1 LDS.128
//   B slice (kk, ntile):  64 words laid out [lane][word] -> fragment = 1 LDS.64
// Word order matches a0..a3 = (g,tig),(g+8,tig),(g,tig+4),(g+8,tig+4);
// b0,b1 = (n=g, k=tig),(n=g, k=tig+4). mma order/values identical to prior rounds.
template<int BM, int BN, int BK, int WM, int WN, int BIAS, int RES, int GELU>
__global__ __launch_bounds__(32*(BM/WM)*(BN/WN))
void mma_gemm(const float* __restrict__ A,
              const float* __restrict__ w0, const float* __restrict__ w1,
              const float* __restrict__ w2,
              const float* __restrict__ bias, const float* __restrict__ res,
              float* __restrict__ C, int M, int Nw, int K, int ldc) {
    constexpr int NWM = BM / WM;
    constexpr int NWN = BN / WN;
    constexpr int NT  = 32 * NWM * NWN;
    constexpr int MT  = WM / 16;
    constexpr int NTn = WN / 8;
    constexpr int KK  = BK / 8;
    constexpr int NMA = BM / 16;          // A m-tiles per kk slice
    constexpr int NNB = BN / 8;           // B n-tiles per kk slice
    constexpr int QA  = BM * BK / 4 / NT;
    constexpr int QB  = BK * BN / 4 / NT;

    __shared__ unsigned As[2][BM * BK];   // KK*NMA*128 == BM*BK
    __shared__ unsigned Bs[2][BN * BK];   // KK*NNB*64  == BN*BK

    const int tid = threadIdx.x;
    const int wid = tid >> 5;
    const int lane = tid & 31;
    const int warp_m = wid % NWM;
    const int warp_n = wid / NWM;
    const int bm = blockIdx.x * BM;
    const int bn_g = blockIdx.y * BN;
    const int sel = bn_g / Nw;
    const int bn_l = bn_g - sel * Nw;
    const float* __restrict__ W = (sel == 0) ? w0 : ((sel == 1) ? w1 : w2);
    const bool vecB = ((Nw & 3) == 0) && (bn_l + BN <= Nw);

    float acc[MT][NTn][4];
    #pragma unroll
    for (int i = 0; i < MT; i++)
        #pragma unroll
        for (int j = 0; j < NTn; j++)
            #pragma unroll
            for (int c = 0; c < 4; c++) acc[i][j][c] = 0.0f;

    // ---- prologue: stage k-tile 0 into buffer 0 (fragment order) ----
    #pragma unroll
    for (int i = 0; i < QA; i++) {
        int idx = tid + i * NT;
        int r  = idx / (BK/4);
        int kq = (idx % (BK/4)) * 4;
        float4 v = *(const float4*)(A + (size_t)(bm + r) * K + kq);
        int kk = kq >> 3, k4 = (kq >> 2) & 1;
        int word = ((r >> 3) & 1) + 2*k4;
        unsigned base = (unsigned)((kk*NMA + (r >> 4)) * 128 + (r & 7) * 16 + word);
        As[0][base     ] = f2tf32(v.x);
        As[0][base +  4] = f2tf32(v.y);
        As[0][base +  8] = f2tf32(v.z);
        As[0][base + 12] = f2tf32(v.w);
    }
    #pragma unroll
    for (int i = 0; i < QB; i++) {
        int idx = tid + i * NT;
        int k  = idx / (BN/4);
        int nq = (idx % (BN/4)) * 4;
        const float* Wr = W + (size_t)k * Nw;
        float v[4];
        if (vecB) {
            float4 t = *(const float4*)(Wr + bn_l + nq);
            v[0] = t.x; v[1] = t.y; v[2] = t.z; v[3] = t.w;
        } else {
            #pragma unroll
            for (int c = 0; c < 4; c++) {
                int col = bn_l + nq + c;
                v[c] = (col < Nw) ? Wr[col] : 0.0f;
            }
        }
        int kk = k >> 3, tig = k & 3, k4 = (k >> 2) & 1;
        #pragma unroll
        for (int c = 0; c < 4; c++) {
            int n = nq + c;
            Bs[0][(kk*NNB + (n >> 3)) * 64 + ((n & 7) * 4 + tig) * 2 + k4] = f2tf32(v[c]);
        }
    }
    __syncthreads();

    int buf = 0;
    for (int k0 = 0; k0 < K; k0 += BK) {
        const bool nxt = (k0 + BK < K);
        float4 pa[QA]; float pb[QB][4];
        if (nxt) {
            #pragma unroll
            for (int i = 0; i < QA; i++) {
                int idx = tid + i * NT;
                int r  = idx / (BK/4);
                int kq = (idx % (BK/4)) * 4;
                pa[i] = *(const float4*)(A + (size_t)(bm + r) * K + k0 + BK + kq);
            }
            #pragma unroll
            for (int i = 0; i < QB; i++) {
                int idx = tid + i * NT;
                int k  = idx / (BN/4);
                int nq = (idx % (BN/4)) * 4;
                const float* Wr = W + (size_t)(k0 + BK + k) * Nw;
                if (vecB) {
                    float4 t = *(const float4*)(Wr + bn_l + nq);
                    pb[i][0] = t.x; pb[i][1] = t.y; pb[i][2] = t.z; pb[i][3] = t.w;
                } else {
                    #pragma unroll
                    for (int c = 0; c < 4; c++) {
                        int col = bn_l + nq + c;
                        pb[i][c] = (col < Nw) ? Wr[col] : 0.0f;
                    }
                }
            }
        }
        // ---- compute on current buffer: 1 LDS.128 per A frag, 1 LDS.64 per B frag ----
        #pragma unroll
        for (int kk = 0; kk < KK; kk++) {
            unsigned afr[MT][4];
            #pragma unroll
            for (int mt = 0; mt < MT; mt++) {
                uint4 av = *(const uint4*)&As[buf][(kk*NMA + warp_m*MT + mt)*128 + lane*4];
                afr[mt][0] = av.x; afr[mt][1] = av.y; afr[mt][2] = av.z; afr[mt][3] = av.w;
            }
            unsigned bfr[NTn][2];
            #pragma unroll
            for (int nt = 0; nt < NTn; nt++) {
                uint2 bv = *(const uint2*)&Bs[buf][(kk*NNB + warp_n*NTn + nt)*64 + lane*2];
                bfr[nt][0] = bv.x; bfr[nt][1] = bv.y;
            }
            #pragma unroll
            for (int mt = 0; mt < MT; mt++)
                #pragma unroll
                for (int nt = 0; nt < NTn; nt++)
                    mma_tf32(acc[mt][nt], afr[mt], bfr[nt]);
        }
        // ---- store prefetched tile (fragment order) ----
        if (nxt) {
            int nb = buf ^ 1;
            #pragma unroll
            for (int i = 0; i < QA; i++) {
                int idx = tid + i * NT;
                int r  = idx / (BK/4);
                int kq = (idx % (BK/4)) * 4;
                int kk = kq >> 3, k4 = (kq >> 2) & 1;
                int word = ((r >> 3) & 1) + 2*k4;
                unsigned base = (unsigned)((kk*NMA + (r >> 4)) * 128 + (r & 7) * 16 + word);
                As[nb][base     ] = f2tf32(pa[i].x);
                As[nb][base +  4] = f2tf32(pa[i].y);
                As[nb][base +  8] = f2tf32(pa[i].z);
                As[nb][base + 12] = f2tf32(pa[i].w);
            }
            #pragma unroll
            for (int i = 0; i < QB; i++) {
                int idx = tid + i * NT;
                int k  = idx / (BN/4);
                int nq = (idx % (BN/4)) * 4;
                int kk = k >> 3, tig = k & 3, k4 = (k >> 2) & 1;
                #pragma unroll
                for (int c = 0; c < 4; c++) {
                    int n = nq + c;
                    Bs[nb][(kk*NNB + (n >> 3)) * 64 + ((n & 7) * 4 + tig) * 2 + k4] = f2tf32(pb[i][c]);
                }
            }
            __syncthreads();
            buf = nb;
        }
    }

    // ---- epilogue ----
    const int g   = lane >> 2;
    const int tig = lane & 3;
    #pragma unroll
    for (int mt = 0; mt < MT; mt++) {
        int row0 = bm + warp_m * WM + mt * 16 + g;
        #pragma unroll
        for (int nt = 0; nt < NTn; nt++) {
            int coff0 = warp_n * WN + nt * 8 + tig * 2;
            #pragma unroll
            for (int c = 0; c < 4; c++) {
                int row  = row0 + (c >= 2 ? 8 : 0);
                int coff = coff0 + (c & 1);
                if (bn_l + coff < Nw) {
                    float v = acc[mt][nt][c];
                    if (BIAS) v += bias[bn_l + coff];
                    if (GELU) v = 0.5f * v * (1.0f + erff(v * 0.70710678118654752f));
                    if (RES)  v += res[(size_t)row * ldc + bn_g + coff];
                    C[(size_t)row * ldc + bn_g + coff] = v;
                }
            }
        }
    }
}

// ---------------- tiled causal attention ----------------
// Block: 64-query tile for one (head, batch). 256 threads; thread (r,cg): row r,
// cols c = 4i+cg (i=0..15). SMEM tiles Q/K/V 64x64, stride 68 (bank-safe for the
// 4-bank-spaced quad access pattern). Online softmax, fp32 exact; AV in f32x2.
// qkv layout: [BT][3*D], q at +0, k at +D, v at +2D, head at h*64.
#define ASTR 68
#define ASMEM (3*64*ASTR*4)
__global__ __launch_bounds__(256)
void attn_kernel(const float* __restrict__ qkv, float* __restrict__ y) {
    extern __shared__ float sm[];
    float* sQ = sm;
    float* sK = sm + 64*ASTR;
    float* sV = sm + 2*64*ASTR;

    const int tid = threadIdx.x;
    const int qt = gridDim.x - 1 - blockIdx.x;   // heavy tiles first
    const int h = blockIdx.y, b = blockIdx.z;
    const int r = tid >> 2, cg = tid & 3;
    const int q0 = qt * 64;
    const int hoff = h * HD_;

    // load Q tile
    #pragma unroll
    for (int j = 0; j < 4; j++) {
        int idx = tid + j*256;
        int rr = idx >> 4, c4 = (idx & 15) * 4;
        *(float4*)&sQ[rr*ASTR + c4] =
            *(const float4*)(qkv + (size_t)(b*T_ + q0 + rr)*(3*D_) + hoff + c4);
    }

    float m = -INFINITY, l = 0.0f;
    ull o2[32];
    #pragma unroll
    for (int d = 0; d < 32; d++) o2[d] = 0ull;

    for (int kt = 0; kt <= qt; kt++) {
        __syncthreads();
        #pragma unroll
        for (int j = 0; j < 4; j++) {
            int idx = tid + j*256;
            int rr = idx >> 4, c4 = (idx & 15) * 4;
            const float* src = qkv + (size_t)(b*T_ + kt*64 + rr)*(3*D_) + hoff + c4;
            *(float4*)&sK[rr*ASTR + c4] = *(const float4*)(src + D_);
            *(float4*)&sV[rr*ASTR + c4] = *(const float4*)(src + 2*D_);
        }
        __syncthreads();

        // scores: s[i] = q[r] . k[4i+cg]
        float s[16];
        #pragma unroll
        for (int i = 0; i < 16; i++) s[i] = 0.0f;
        #pragma unroll
        for (int d4 = 0; d4 < 16; d4++) {
            float4 q4 = *(const float4*)&sQ[r*ASTR + d4*4];
            #pragma unroll
            for (int i = 0; i < 16; i++) {
                float4 k4 = *(const float4*)&sK[(4*i+cg)*ASTR + d4*4];
                s[i] += q4.x*k4.x + q4.y*k4.y + q4.z*k4.z + q4.w*k4.w;
            }
        }
        const bool diag = (kt == qt);
        float smax = -INFINITY;
        #pragma unroll
        for (int i = 0; i < 16; i++) {
            float v = s[i] * 0.125f;
            if (diag && (4*i+cg) > r) v = -INFINITY;
            s[i] = v;
            smax = fmaxf(smax, v);
        }
        smax = fmaxf(smax, __shfl_xor_sync(0xffffffffu, smax, 1));
        smax = fmaxf(smax, __shfl_xor_sync(0xffffffffu, smax, 2));
        float mnew = fmaxf(m, smax);
        float corr = __expf(m - mnew);
        float psum = 0.0f;
        #pragma unroll
        for (int i = 0; i < 16; i++) {
            s[i] = __expf(s[i] - mnew);
            psum += s[i];
        }
        psum += __shfl_xor_sync(0xffffffffu, psum, 1);
        psum += __shfl_xor_sync(0xffffffffu, psum, 2);
        l = l * corr + psum;
        m = mnew;

        ull c2 = splat2(corr);
        #pragma unroll
        for (int d = 0; d < 32; d++) mul2(o2[d], c2);
        #pragma unroll
        for (int i = 0; i < 16; i++) {
            ull p2 = splat2(s[i]);
            const float* vrow = &sV[(4*i+cg)*ASTR];
            #pragma unroll
            for (int d4 = 0; d4 < 16; d4++) {
                float4 v4 = *(const float4*)&vrow[d4*4];
                fma2(o2[2*d4  ], p2, pack2(v4.x, v4.y));
                fma2(o2[2*d4+1], p2, pack2(v4.z, v4.w));
            }
        }
    }

    // quad-reduce output, stage in sK, coalesced store
    __syncthreads();
    float inv = 1.0f / l;
    #pragma unroll
    for (int d = 0; d < 32; d++) {
        float lo, hi;
        unpack2(o2[d], lo, hi);
        lo += __shfl_xor_sync(0xffffffffu, lo, 1);
        lo += __shfl_xor_sync(0xffffffffu, lo, 2);
        hi += __shfl_xor_sync(0xffffffffu, hi, 1);
        hi += __shfl_xor_sync(0xffffffffu, hi, 2);
        if (cg == 0) {
            sK[r*ASTR + 2*d    ] = lo * inv;
            sK[r*ASTR + 2*d + 1] = hi * inv;
        }
    }
    __syncthreads();
    #pragma unroll
    for (int j = 0; j < 4; j++) {
        int idx = tid + j*256;
        int rr = idx >> 4, c4 = (idx & 15) * 4;
        *(float4*)(y + (size_t)(b*T_ + q0 + rr)*D_ + hoff + c4) =
            *(float4*)&sK[rr*ASTR + c4];
    }
}

// ---------------- host orchestration ----------------
extern "C" void kernel_launch(void* const* d_in, const int* in_sizes, int n_in,
                              void* d_out, int out_size) {
    const int*   idx  = (const int*)  d_in[0];
    const float* tok  = (const float*)d_in[1];
    const float* pos  = (const float*)d_in[2];
    const float* Wq   = (const float*)d_in[3];
    const float* Wk   = (const float*)d_in[4];
    const float* Wv   = (const float*)d_in[5];
    const float* Wo   = (const float*)d_in[6];
    const float* bo   = (const float*)d_in[7];
    const float* ln1g = (const float*)d_in[8];
    const float* ln1b = (const float*)d_in[9];
    const float* Wf1  = (const float*)d_in[10];
    const float* bf1  = (const float*)d_in[11];
    const float* Wf2  = (const float*)d_in[12];
    const float* bf2  = (const float*)d_in[13];
    const float* ln2g = (const float*)d_in[14];
    const float* ln2b = (const float*)d_in[15];
    const float* lnfg = (const float*)d_in[16];
    const float* lnfb = (const float*)d_in[17];
    const float* Wlm  = (const float*)d_in[18];
    float* out = (float*)d_out;

    float *x, *h, *qkvb, *yb, *ffb;
    cudaGetSymbolAddress((void**)&x,    g_x);
    cudaGetSymbolAddress((void**)&h,    g_h);
    cudaGetSymbolAddress((void**)&qkvb, g_qkv);
    cudaGetSymbolAddress((void**)&yb,   g_y);
    cudaGetSymbolAddress((void**)&ffb,  g_ff);

    cudaFuncSetAttribute(attn_kernel, cudaFuncAttributeMaxDynamicSharedMemorySize, ASMEM);

    const dim3 gQKV(BT_/64, 3*D_/64);      // 32 x 36 = 1152 blocks
    const dim3 gS(BT_/64, D_/64);          // 32 x 12 = 384 blocks
    const dim3 gF1(BT_/128, FF_/128);      // 16 x 24 = 384 blocks
    const dim3 gLM(BT_/128, (V_+127)/128); // 16 x 393

    embed_kernel<<<(BT_*D_ + 255)/256, 256>>>(idx, tok, pos, x);

    for (int l = 0; l < L_; l++) {
        const float* wq  = Wq  + (size_t)l*D_*D_;
        const float* wk  = Wk  + (size_t)l*D_*D_;
        const float* wv  = Wv  + (size_t)l*D_*D_;
        const float* wo  = Wo  + (size_t)l*D_*D_;
        const float* wf1 = Wf1 + (size_t)l*D_*FF_;
        const float* wf2 = Wf2 + (size_t)l*FF_*D_;

        ln_kernel<<<BT_, 256>>>(x, ln1g + l*D_, ln1b + l*D_, h);
        // fused QKV: one GEMM, output [BT, 3*D]
        mma_gemm<64,64,32,32,32,0,0,0><<<gQKV, 128>>>(h, wq, wk, wv,
            nullptr, nullptr, qkvb, BT_, D_, D_, 3*D_);
        attn_kernel<<<dim3(T_/64, H_, B_), 256, ASMEM>>>(qkvb, yb);
        mma_gemm<64,64,32,32,32,1,1,0><<<gS, 128>>>(yb, wo, wo, wo,
            bo + l*D_, x, x, BT_, D_, D_, D_);
        ln_kernel<<<BT_, 256>>>(x, ln2g + l*D_, ln2b + l*D_, h);
        mma_gemm<128,128,16,64,32,1,0,1><<<gF1, 256>>>(h, wf1, wf1, wf1,
            bf1 + l*FF_, nullptr, ffb, BT_, FF_, D_, FF_);
        mma_gemm<64,64,32,32,32,1,1,0><<<gS, 128>>>(ffb, wf2, wf2, wf2,
            bf2 + l*D_, x, x, BT_, D_, FF_, D_);
    }

    ln_kernel<<<BT_, 256>>>(x, lnfg, lnfb, h);
    mma_gemm<128,128,16,64,32,0,0,0><<<gLM, 256>>>(h, Wlm, Wlm, Wlm,
        nullptr, nullptr, out, BT_, V_, D_, V_);
}